// round 14
// baseline (speedup 1.0000x reference)
#include <cuda_runtime.h>
#include <cuda_fp16.h>
#include <cstdint>

#define Nn 100000
#define Ee 1600000
#define Hh 128
#define Cc 47
#define Ll 3
#define BN_EPS 1e-5f
#define NTILES 1563          // ceil(Nn/64)
#define GPERS 296            // 2 CTAs per SM * 148

// ---------------- device scratch (no allocations allowed) ----------------
__device__ __half g_h16[(size_t)Nn * Hh];   // fp16 features for gather / final GEMM
__device__ float  g_agg[(size_t)Nn * Hh];   // aggregated features
__device__ int    g_csr[Ee];                // src ids grouped by dst
__device__ int    g_off[Nn + 1];            // CSR row offsets (by dst)
__device__ int    g_deg_in[Nn];
__device__ int    g_deg_out[Nn];
__device__ int    g_cur[Nn];
__device__ float  g_nsrc[Nn];
__device__ float  g_ndst[Nn];
__device__ int    g_bsum[256];

// ---------------- f32x2 helpers ----------------
__device__ __forceinline__ void ffma2(uint64_t& d, uint64_t a, uint64_t b) {
    asm("fma.rn.f32x2 %0, %1, %2, %0;" : "+l"(d) : "l"(a), "l"(b));
}
__device__ __forceinline__ uint64_t dup2(float x) {
    uint64_t r; asm("mov.b64 %0, {%1, %1};" : "=l"(r) : "f"(x)); return r;
}
__device__ __forceinline__ float2 unpack2(uint64_t v) {
    float2 f; asm("mov.b64 {%0, %1}, %2;" : "=f"(f.x), "=f"(f.y) : "l"(v)); return f;
}
__device__ __forceinline__ uint32_t h2_bits(__half2 h) {
    uint32_t u; memcpy(&u, &h, 4); return u;
}

// ---------------- setup kernels ----------------
__global__ void k_zero3() {
    int i = blockIdx.x * blockDim.x + threadIdx.x;
    if (i < Nn) { g_deg_in[i] = 0; g_deg_out[i] = 0; g_cur[i] = 0; }
}

__global__ void k_deg(const int* __restrict__ src, const int* __restrict__ dst) {
    int e = blockIdx.x * blockDim.x + threadIdx.x;
    if (e < Ee) {
        atomicAdd(&g_deg_out[src[e]], 1);
        atomicAdd(&g_deg_in[dst[e]], 1);
    }
}

__global__ void k_norms() {
    int i = blockIdx.x * blockDim.x + threadIdx.x;
    if (i < Nn) {
        g_nsrc[i] = rsqrtf(fmaxf((float)g_deg_out[i], 1.0f));
        g_ndst[i] = rsqrtf(fmaxf((float)g_deg_in[i], 1.0f));
    }
}

__global__ void k_scan1() {
    __shared__ int s[512];
    int i = blockIdx.x * 512 + threadIdx.x;
    int v = (i < Nn) ? g_deg_in[i] : 0;
    s[threadIdx.x] = v;
    __syncthreads();
    for (int off = 1; off < 512; off <<= 1) {
        int t = (threadIdx.x >= off) ? s[threadIdx.x - off] : 0;
        __syncthreads();
        s[threadIdx.x] += t;
        __syncthreads();
    }
    if (i < Nn) g_off[i] = s[threadIdx.x] - v;   // exclusive
    if (threadIdx.x == 511) g_bsum[blockIdx.x] = s[511];
}

__global__ void k_scan2(int nblk) {
    if (threadIdx.x == 0 && blockIdx.x == 0) {
        int run = 0;
        for (int b = 0; b < nblk; b++) { int t = g_bsum[b]; g_bsum[b] = run; run += t; }
    }
}

__global__ void k_scan3() {
    int i = blockIdx.x * 512 + threadIdx.x;
    if (i < Nn) g_off[i] += g_bsum[blockIdx.x];
    if (i == 0) g_off[Nn] = Ee;
}

__global__ void k_fill(const int* __restrict__ src, const int* __restrict__ dst) {
    int e = blockIdx.x * blockDim.x + threadIdx.x;
    if (e < Ee) {
        int d = dst[e];
        int p = atomicAdd(&g_cur[d], 1);
        g_csr[g_off[d] + p] = src[e];
    }
}

// ---------------- persistent GEMM 128x128 + BN + ReLU (smem W loaded once) ----------------
// 296 CTAs, 256 threads (8 warps), each CTA loops 64-row tiles.
// 8 rows x 4 cols per lane, FFMA2 inner loop. Writes fp16 (prescaled by snorm if non-null).
__global__ void __launch_bounds__(256) k_gemm128(
    const float* __restrict__ X, const float* __restrict__ W,
    const float* __restrict__ blin,
    const float* __restrict__ gm, const float* __restrict__ bt,
    const float* __restrict__ rm, const float* __restrict__ rv,
    const float* __restrict__ snorm, __half* __restrict__ Yh)
{
    extern __shared__ float smem[];
    float* Ws = smem;               // 128*128
    float* Xs = smem + 128 * 128;   // 64*128
    float* sc = Xs + 64 * 128;      // 128
    float* sh = sc + 128;           // 128

    int tid = threadIdx.x;
    if (tid < 128) {
        float inv = rsqrtf(rv[tid] + BN_EPS);
        float s = gm[tid] * inv;
        sc[tid] = s;
        sh[tid] = bt[tid] + (blin[tid] - rm[tid]) * s;
    }
    const float4* W4 = (const float4*)W;
    float4* Ws4 = (float4*)Ws;
#pragma unroll
    for (int p = 0; p < 16; p++) Ws4[tid + p * 256] = W4[tid + p * 256];

    int warp = tid >> 5, lane = tid & 31;
    int r0 = warp * 8;
    const float4* X4 = (const float4*)X;
    float4* Xs4 = (float4*)Xs;

    for (int t = blockIdx.x; t < NTILES; t += GPERS) {
        int base = t * 64;

        __syncthreads();   // previous tile's reads of Xs complete (also orders W/sc on iter 0)
#pragma unroll
        for (int p = 0; p < 8; p++) {
            int idx = tid + p * 256;          // 0..2047 float4s
            int row = base + (idx >> 5);
            if (row >= Nn) row = Nn - 1;
            Xs4[idx] = X4[(size_t)row * 32 + (idx & 31)];
        }
        __syncthreads();

        uint64_t acc[8][2];
#pragma unroll
        for (int r = 0; r < 8; r++) { acc[r][0] = 0ull; acc[r][1] = 0ull; }

#pragma unroll 2
        for (int kk = 0; kk < 128; kk += 4) {
            float4 a4[8];
#pragma unroll
            for (int r = 0; r < 8; r++) a4[r] = *(const float4*)&Xs[(r0 + r) * 128 + kk];
#pragma unroll
            for (int u = 0; u < 4; u++) {
                ulonglong2 w = *(const ulonglong2*)&Ws[(kk + u) * 128 + lane * 4];
#pragma unroll
                for (int r = 0; r < 8; r++) {
                    float a = (u == 0) ? a4[r].x : (u == 1) ? a4[r].y : (u == 2) ? a4[r].z : a4[r].w;
                    uint64_t a2 = dup2(a);
                    ffma2(acc[r][0], a2, w.x);
                    ffma2(acc[r][1], a2, w.y);
                }
            }
        }

        float4 s4 = *(const float4*)&sc[lane * 4];
        float4 h4 = *(const float4*)&sh[lane * 4];
#pragma unroll
        for (int r = 0; r < 8; r++) {
            int row = base + r0 + r;
            if (row >= Nn) break;
            float2 lo = unpack2(acc[r][0]);
            float2 hi = unpack2(acc[r][1]);
            float4 y;
            y.x = fmaxf(fmaf(lo.x, s4.x, h4.x), 0.f);
            y.y = fmaxf(fmaf(lo.y, s4.y, h4.y), 0.f);
            y.z = fmaxf(fmaf(hi.x, s4.z, h4.z), 0.f);
            y.w = fmaxf(fmaf(hi.y, s4.w, h4.w), 0.f);
            float f = snorm ? snorm[row] : 1.0f;
            __half2 p0 = __floats2half2_rn(y.x * f, y.y * f);
            __half2 p1 = __floats2half2_rn(y.z * f, y.w * f);
            uint2 pk = make_uint2(h2_bits(p0), h2_bits(p1));
            *(uint2*)&Yh[(size_t)row * 128 + lane * 4] = pk;
        }
    }
}

// ---------------- aggregation: warp per dst node, batched-prefetch fp16 gather ----------------
// If snorm != null, each gathered row is scaled by snorm[src] (used when h is unscaled).
__global__ void __launch_bounds__(256) k_agg(const float* __restrict__ snorm) {
    int w = (blockIdx.x * 256 + threadIdx.x) >> 5;
    int lane = threadIdx.x & 31;
    if (w >= Nn) return;
    int s0 = g_off[w], s1 = g_off[w + 1];
    const uint2* h2 = (const uint2*)g_h16;   // 32 uint2 per row (4 halfs per lane)
    float4 acc = make_float4(0.f, 0.f, 0.f, 0.f);

    int e = s0;
    for (; e + 8 <= s1; e += 8) {
        int idx[8];
#pragma unroll
        for (int j = 0; j < 8; j++) idx[j] = g_csr[e + j];
        uint2 v[8];
#pragma unroll
        for (int j = 0; j < 8; j++) v[j] = h2[(size_t)idx[j] * 32 + lane];
        if (snorm) {
            float ns[8];
#pragma unroll
            for (int j = 0; j < 8; j++) ns[j] = snorm[idx[j]];
#pragma unroll
            for (int j = 0; j < 8; j++) {
                float2 fa = __half22float2(*(__half2*)&v[j].x);
                float2 fb = __half22float2(*(__half2*)&v[j].y);
                acc.x = fmaf(fa.x, ns[j], acc.x);
                acc.y = fmaf(fa.y, ns[j], acc.y);
                acc.z = fmaf(fb.x, ns[j], acc.z);
                acc.w = fmaf(fb.y, ns[j], acc.w);
            }
        } else {
#pragma unroll
            for (int j = 0; j < 8; j++) {
                float2 fa = __half22float2(*(__half2*)&v[j].x);
                float2 fb = __half22float2(*(__half2*)&v[j].y);
                acc.x += fa.x; acc.y += fa.y; acc.z += fb.x; acc.w += fb.y;
            }
        }
    }
    for (; e < s1; e++) {
        int s = g_csr[e];
        uint2 v = h2[(size_t)s * 32 + lane];
        float ns = snorm ? snorm[s] : 1.0f;
        float2 fa = __half22float2(*(__half2*)&v.x);
        float2 fb = __half22float2(*(__half2*)&v.y);
        acc.x = fmaf(fa.x, ns, acc.x);
        acc.y = fmaf(fa.y, ns, acc.y);
        acc.z = fmaf(fb.x, ns, acc.z);
        acc.w = fmaf(fb.y, ns, acc.w);
    }

    float nd = g_ndst[w];
    acc.x *= nd; acc.y *= nd; acc.z *= nd; acc.w *= nd;
    ((float4*)g_agg)[(size_t)w * 32 + lane] = acc;
}

// ---------------- final GEMM 128x47 + bias (fp16 input) ----------------
__global__ void __launch_bounds__(256) k_gemm_out(
    const __half* __restrict__ X, const float* __restrict__ W,
    const float* __restrict__ b, float* __restrict__ Y)
{
    __shared__ float Ws[128 * 47];
    __shared__ __half Xs[32 * 128];
    int tid = threadIdx.x;
    for (int i = tid; i < 128 * 47; i += 256) Ws[i] = W[i];
    const uint4* X4 = (const uint4*)(X + (size_t)blockIdx.x * 32 * 128);  // 8 halfs each
    uint4* Xs4 = (uint4*)Xs;
#pragma unroll
    for (int p = 0; p < 2; p++) Xs4[tid + p * 256] = X4[tid + p * 256];
    __syncthreads();

    int warp = tid >> 5, lane = tid & 31;
    int r0 = warp * 4;
    bool two = (lane + 32) < Cc;
#pragma unroll
    for (int r = 0; r < 4; r++) {
        int row = blockIdx.x * 32 + r0 + r;
        const __half2* xr = (const __half2*)&Xs[(r0 + r) * 128];
        float a0 = 0.f, a1 = 0.f;
#pragma unroll 4
        for (int k2 = 0; k2 < 64; k2++) {
            float2 aa = __half22float2(xr[k2]);
            a0 = fmaf(aa.x, Ws[(2 * k2) * 47 + lane], a0);
            a0 = fmaf(aa.y, Ws[(2 * k2 + 1) * 47 + lane], a0);
            if (two) {
                a1 = fmaf(aa.x, Ws[(2 * k2) * 47 + lane + 32], a1);
                a1 = fmaf(aa.y, Ws[(2 * k2 + 1) * 47 + lane + 32], a1);
            }
        }
        Y[(size_t)row * Cc + lane] = a0 + b[lane];
        if (two) Y[(size_t)row * Cc + lane + 32] = a1 + b[lane + 32];
    }
}

// ---------------- launch ----------------
extern "C" void kernel_launch(void* const* d_in, const int* in_sizes, int n_in,
                              void* d_out, int out_size)
{
    const float* feat  = (const float*)d_in[0];
    const int*   src   = (const int*)d_in[1];
    const int*   dst   = (const int*)d_in[2];
    const float* W_in  = (const float*)d_in[3];
    const float* b_in  = (const float*)d_in[4];
    const float* Wc    = (const float*)d_in[5];
    const float* bc    = (const float*)d_in[6];
    const float* gamma = (const float*)d_in[7];
    const float* beta  = (const float*)d_in[8];
    const float* rmean = (const float*)d_in[9];
    const float* rvar  = (const float*)d_in[10];
    const float* W_out = (const float*)d_in[11];
    const float* b_out = (const float*)d_in[12];
    float* out = (float*)d_out;

    float *ap = nullptr, *np = nullptr;
    __half* h16p = nullptr;
    cudaGetSymbolAddress((void**)&ap, g_agg);
    cudaGetSymbolAddress((void**)&np, g_nsrc);
    cudaGetSymbolAddress((void**)&h16p, g_h16);

    // lazy one-time side stream + fork/join events (no device memory involved)
    static cudaStream_t sB = nullptr;
    static cudaEvent_t evF = nullptr, evJ = nullptr;
    if (!sB) {
        cudaStreamCreateWithFlags(&sB, cudaStreamNonBlocking);
        cudaEventCreateWithFlags(&evF, cudaEventDisableTiming);
        cudaEventCreateWithFlags(&evJ, cudaEventDisableTiming);
    }

    const int NBLK = (Nn + 511) / 512;  // 196
    const size_t gemm_smem = (size_t)(128 * 128 + 64 * 128 + 256) * sizeof(float);
    cudaFuncSetAttribute(k_gemm128, cudaFuncAttributeMaxDynamicSharedMemorySize, (int)gemm_smem);

    // Fork at t=0: ALL graph setup on side stream, input GEMM (no nsrc dependency)
    // starts immediately on stream 0 and hides the whole setup chain.
    cudaEventRecord(evF, 0);
    cudaStreamWaitEvent(sB, evF, 0);
    k_zero3<<<(Nn + 255) / 256, 256, 0, sB>>>();
    k_deg<<<(Ee + 255) / 256, 256, 0, sB>>>(src, dst);
    k_norms<<<(Nn + 255) / 256, 256, 0, sB>>>();
    k_scan1<<<NBLK, 512, 0, sB>>>();
    k_scan2<<<1, 32, 0, sB>>>(NBLK);
    k_scan3<<<NBLK, 512, 0, sB>>>();
    k_fill<<<(Ee + 255) / 256, 256, 0, sB>>>(src, dst);
    cudaEventRecord(evJ, sB);

    // input projection -> h16 (UNSCALED; nsrc applied in layer-1 agg)
    k_gemm128<<<GPERS, 256, gemm_smem>>>(feat, W_in, b_in,
                                         gamma, beta, rmean, rvar, nullptr, h16p);

    // join setup before first aggregation
    cudaStreamWaitEvent(0, evJ, 0);

    // 3 GraphConv layers
    for (int l = 0; l < Ll; l++) {
        // layer 0: h16 is unscaled -> apply nsrc per edge; later layers: prescaled
        k_agg<<<(Nn * 32 + 255) / 256, 256>>>(l == 0 ? np : nullptr);
        bool last = (l == Ll - 1);
        k_gemm128<<<GPERS, 256, gemm_smem>>>(ap, Wc + (size_t)l * Hh * Hh, bc + (size_t)l * Hh,
                                             gamma + (size_t)(l + 1) * Hh,
                                             beta  + (size_t)(l + 1) * Hh,
                                             rmean + (size_t)(l + 1) * Hh,
                                             rvar  + (size_t)(l + 1) * Hh,
                                             last ? nullptr : np, h16p);
    }

    // output projection (fp16 input)
    k_gemm_out<<<Nn / 32, 256>>>(h16p, W_out, b_out, out);
}

// round 15
// speedup vs baseline: 1.1595x; 1.1595x over previous
#include <cuda_runtime.h>
#include <cuda_fp16.h>
#include <cstdint>

#define Nn 100000
#define Ee 1600000
#define Hh 128
#define Cc 47
#define Ll 3
#define BN_EPS 1e-5f
#define NTILES 1563          // ceil(Nn/64)
#define GPERS 296            // 2 CTAs per SM * 148

// ---------------- device scratch (no allocations allowed) ----------------
__device__ __half g_h16[(size_t)Nn * Hh];   // fp16 features for gather / final GEMM
__device__ float  g_agg[(size_t)Nn * Hh];   // aggregated features
__device__ int    g_csr[Ee];                // src ids grouped by dst
__device__ int    g_off[Nn + 1];            // CSR row offsets (by dst)
__device__ int    g_deg_in[Nn];
__device__ int    g_deg_out[Nn];
__device__ int    g_cur[Nn];
__device__ float  g_nsrc[Nn];
__device__ float  g_ndst[Nn];
__device__ int    g_bsum[256];

// ---------------- f32x2 helpers ----------------
__device__ __forceinline__ void ffma2(uint64_t& d, uint64_t a, uint64_t b) {
    asm("fma.rn.f32x2 %0, %1, %2, %0;" : "+l"(d) : "l"(a), "l"(b));
}
__device__ __forceinline__ uint64_t dup2(float x) {
    uint64_t r; asm("mov.b64 %0, {%1, %1};" : "=l"(r) : "f"(x)); return r;
}
__device__ __forceinline__ float2 unpack2(uint64_t v) {
    float2 f; asm("mov.b64 {%0, %1}, %2;" : "=f"(f.x), "=f"(f.y) : "l"(v)); return f;
}
__device__ __forceinline__ uint32_t h2_bits(__half2 h) {
    uint32_t u; memcpy(&u, &h, 4); return u;
}

// ---------------- setup kernels ----------------
__global__ void k_zero3() {
    int i = blockIdx.x * blockDim.x + threadIdx.x;
    if (i < Nn) { g_deg_in[i] = 0; g_deg_out[i] = 0; g_cur[i] = 0; }
}

__global__ void k_deg(const int* __restrict__ src, const int* __restrict__ dst) {
    int e = blockIdx.x * blockDim.x + threadIdx.x;
    if (e < Ee) {
        atomicAdd(&g_deg_out[src[e]], 1);
        atomicAdd(&g_deg_in[dst[e]], 1);
    }
}

__global__ void k_norms() {
    int i = blockIdx.x * blockDim.x + threadIdx.x;
    if (i < Nn) {
        g_nsrc[i] = rsqrtf(fmaxf((float)g_deg_out[i], 1.0f));
        g_ndst[i] = rsqrtf(fmaxf((float)g_deg_in[i], 1.0f));
    }
}

__global__ void k_scan1() {
    __shared__ int s[512];
    int i = blockIdx.x * 512 + threadIdx.x;
    int v = (i < Nn) ? g_deg_in[i] : 0;
    s[threadIdx.x] = v;
    __syncthreads();
    for (int off = 1; off < 512; off <<= 1) {
        int t = (threadIdx.x >= off) ? s[threadIdx.x - off] : 0;
        __syncthreads();
        s[threadIdx.x] += t;
        __syncthreads();
    }
    if (i < Nn) g_off[i] = s[threadIdx.x] - v;   // exclusive
    if (threadIdx.x == 511) g_bsum[blockIdx.x] = s[511];
}

__global__ void k_scan2(int nblk) {
    if (threadIdx.x == 0 && blockIdx.x == 0) {
        int run = 0;
        for (int b = 0; b < nblk; b++) { int t = g_bsum[b]; g_bsum[b] = run; run += t; }
    }
}

__global__ void k_scan3() {
    int i = blockIdx.x * 512 + threadIdx.x;
    if (i < Nn) g_off[i] += g_bsum[blockIdx.x];
    if (i == 0) g_off[Nn] = Ee;
}

__global__ void k_fill(const int* __restrict__ src, const int* __restrict__ dst) {
    int e = blockIdx.x * blockDim.x + threadIdx.x;
    if (e < Ee) {
        int d = dst[e];
        int p = atomicAdd(&g_cur[d], 1);
        g_csr[g_off[d] + p] = src[e];
    }
}

// ---------------- persistent GEMM 128x128 + BN + ReLU (smem W, X reg-prefetch) ----------------
// 296 CTAs, 256 threads (8 warps), each CTA loops 64-row tiles.
// 8 rows x 4 cols per lane, FFMA2 inner loop. Writes fp16 (prescaled by snorm if non-null).
__global__ void __launch_bounds__(256, 2) k_gemm128(
    const float* __restrict__ X, const float* __restrict__ W,
    const float* __restrict__ blin,
    const float* __restrict__ gm, const float* __restrict__ bt,
    const float* __restrict__ rm, const float* __restrict__ rv,
    const float* __restrict__ snorm, __half* __restrict__ Yh)
{
    extern __shared__ float smem[];
    float* Ws = smem;               // 128*128
    float* Xs = smem + 128 * 128;   // 64*128
    float* sc = Xs + 64 * 128;      // 128
    float* sh = sc + 128;           // 128

    int tid = threadIdx.x;
    if (tid < 128) {
        float inv = rsqrtf(rv[tid] + BN_EPS);
        float s = gm[tid] * inv;
        sc[tid] = s;
        sh[tid] = bt[tid] + (blin[tid] - rm[tid]) * s;
    }
    const float4* W4 = (const float4*)W;
    float4* Ws4 = (float4*)Ws;
#pragma unroll
    for (int p = 0; p < 16; p++) Ws4[tid + p * 256] = W4[tid + p * 256];

    int warp = tid >> 5, lane = tid & 31;
    int r0 = warp * 8;
    const float4* X4 = (const float4*)X;
    float4* Xs4 = (float4*)Xs;

    int t = blockIdx.x;
    float4 xr[8];
    if (t < NTILES) {
#pragma unroll
        for (int p = 0; p < 8; p++) {
            int idx = tid + p * 256;
            int row = t * 64 + (idx >> 5);
            if (row >= Nn) row = Nn - 1;
            xr[p] = X4[(size_t)row * 32 + (idx & 31)];
        }
    }

    while (t < NTILES) {
        int base = t * 64;

        __syncthreads();   // previous tile's reads of Xs complete (also orders W/sc on iter 0)
#pragma unroll
        for (int p = 0; p < 8; p++) Xs4[tid + p * 256] = xr[p];
        __syncthreads();

        // prefetch next tile's X into registers (hidden under compute)
        int tn = t + GPERS;
        if (tn < NTILES) {
#pragma unroll
            for (int p = 0; p < 8; p++) {
                int idx = tid + p * 256;
                int row = tn * 64 + (idx >> 5);
                if (row >= Nn) row = Nn - 1;
                xr[p] = X4[(size_t)row * 32 + (idx & 31)];
            }
        }

        uint64_t acc[8][2];
#pragma unroll
        for (int r = 0; r < 8; r++) { acc[r][0] = 0ull; acc[r][1] = 0ull; }

#pragma unroll 2
        for (int kk = 0; kk < 128; kk += 4) {
            float4 a4[8];
#pragma unroll
            for (int r = 0; r < 8; r++) a4[r] = *(const float4*)&Xs[(r0 + r) * 128 + kk];
#pragma unroll
            for (int u = 0; u < 4; u++) {
                ulonglong2 w = *(const ulonglong2*)&Ws[(kk + u) * 128 + lane * 4];
#pragma unroll
                for (int r = 0; r < 8; r++) {
                    float a = (u == 0) ? a4[r].x : (u == 1) ? a4[r].y : (u == 2) ? a4[r].z : a4[r].w;
                    uint64_t a2 = dup2(a);
                    ffma2(acc[r][0], a2, w.x);
                    ffma2(acc[r][1], a2, w.y);
                }
            }
        }

        float4 s4 = *(const float4*)&sc[lane * 4];
        float4 h4 = *(const float4*)&sh[lane * 4];
#pragma unroll
        for (int r = 0; r < 8; r++) {
            int row = base + r0 + r;
            if (row >= Nn) break;
            float2 lo = unpack2(acc[r][0]);
            float2 hi = unpack2(acc[r][1]);
            float4 y;
            y.x = fmaxf(fmaf(lo.x, s4.x, h4.x), 0.f);
            y.y = fmaxf(fmaf(lo.y, s4.y, h4.y), 0.f);
            y.z = fmaxf(fmaf(hi.x, s4.z, h4.z), 0.f);
            y.w = fmaxf(fmaf(hi.y, s4.w, h4.w), 0.f);
            float f = snorm ? snorm[row] : 1.0f;
            __half2 p0 = __floats2half2_rn(y.x * f, y.y * f);
            __half2 p1 = __floats2half2_rn(y.z * f, y.w * f);
            uint2 pk = make_uint2(h2_bits(p0), h2_bits(p1));
            *(uint2*)&Yh[(size_t)row * 128 + lane * 4] = pk;
        }
        t = tn;
    }
}

// ---------------- aggregation: warp per dst node, batched-prefetch fp16 gather ----------------
__global__ void __launch_bounds__(256) k_agg() {
    int w = (blockIdx.x * 256 + threadIdx.x) >> 5;
    int lane = threadIdx.x & 31;
    if (w >= Nn) return;
    int s0 = g_off[w], s1 = g_off[w + 1];
    const uint2* h2 = (const uint2*)g_h16;   // 32 uint2 per row (4 halfs per lane)
    float4 acc = make_float4(0.f, 0.f, 0.f, 0.f);

    int e = s0;
    for (; e + 8 <= s1; e += 8) {
        int idx[8];
#pragma unroll
        for (int j = 0; j < 8; j++) idx[j] = g_csr[e + j];
        uint2 v[8];
#pragma unroll
        for (int j = 0; j < 8; j++) v[j] = h2[(size_t)idx[j] * 32 + lane];
#pragma unroll
        for (int j = 0; j < 8; j++) {
            float2 fa = __half22float2(*(__half2*)&v[j].x);
            float2 fb = __half22float2(*(__half2*)&v[j].y);
            acc.x += fa.x; acc.y += fa.y; acc.z += fb.x; acc.w += fb.y;
        }
    }
    for (; e < s1; e++) {
        int s = g_csr[e];
        uint2 v = h2[(size_t)s * 32 + lane];
        float2 fa = __half22float2(*(__half2*)&v.x);
        float2 fb = __half22float2(*(__half2*)&v.y);
        acc.x += fa.x; acc.y += fa.y; acc.z += fb.x; acc.w += fb.y;
    }

    float nd = g_ndst[w];
    acc.x *= nd; acc.y *= nd; acc.z *= nd; acc.w *= nd;
    ((float4*)g_agg)[(size_t)w * 32 + lane] = acc;
}

// ---------------- final GEMM 128x47 + bias (fp16 input, k-outer loop) ----------------
__global__ void __launch_bounds__(256) k_gemm_out(
    const __half* __restrict__ X, const float* __restrict__ W,
    const float* __restrict__ b, float* __restrict__ Y)
{
    __shared__ float Ws[128 * 47];
    __shared__ __half Xs[32 * 128];
    int tid = threadIdx.x;
    for (int i = tid; i < 128 * 47; i += 256) Ws[i] = W[i];
    const uint4* X4 = (const uint4*)(X + (size_t)blockIdx.x * 32 * 128);  // 8 halfs each
    uint4* Xs4 = (uint4*)Xs;
#pragma unroll
    for (int p = 0; p < 2; p++) Xs4[tid + p * 256] = X4[tid + p * 256];
    __syncthreads();

    int warp = tid >> 5, lane = tid & 31;
    int r0 = warp * 4;
    bool two = (lane + 32) < Cc;
    const __half2* xr0 = (const __half2*)&Xs[(r0 + 0) * 128];
    const __half2* xr1 = (const __half2*)&Xs[(r0 + 1) * 128];
    const __half2* xr2 = (const __half2*)&Xs[(r0 + 2) * 128];
    const __half2* xr3 = (const __half2*)&Xs[(r0 + 3) * 128];

    float a0[4] = {0.f, 0.f, 0.f, 0.f};
    float a1[4] = {0.f, 0.f, 0.f, 0.f};
#pragma unroll 4
    for (int k2 = 0; k2 < 64; k2++) {
        float w00 = Ws[(2 * k2) * 47 + lane];
        float w01 = Ws[(2 * k2 + 1) * 47 + lane];
        float w10 = two ? Ws[(2 * k2) * 47 + lane + 32] : 0.f;
        float w11 = two ? Ws[(2 * k2 + 1) * 47 + lane + 32] : 0.f;
        float2 x0 = __half22float2(xr0[k2]);
        float2 x1 = __half22float2(xr1[k2]);
        float2 x2 = __half22float2(xr2[k2]);
        float2 x3 = __half22float2(xr3[k2]);
        a0[0] = fmaf(x0.x, w00, fmaf(x0.y, w01, a0[0]));
        a0[1] = fmaf(x1.x, w00, fmaf(x1.y, w01, a0[1]));
        a0[2] = fmaf(x2.x, w00, fmaf(x2.y, w01, a0[2]));
        a0[3] = fmaf(x3.x, w00, fmaf(x3.y, w01, a0[3]));
        a1[0] = fmaf(x0.x, w10, fmaf(x0.y, w11, a1[0]));
        a1[1] = fmaf(x1.x, w10, fmaf(x1.y, w11, a1[1]));
        a1[2] = fmaf(x2.x, w10, fmaf(x2.y, w11, a1[2]));
        a1[3] = fmaf(x3.x, w10, fmaf(x3.y, w11, a1[3]));
    }
#pragma unroll
    for (int r = 0; r < 4; r++) {
        int row = blockIdx.x * 32 + r0 + r;
        Y[(size_t)row * Cc + lane] = a0[r] + b[lane];
        if (two) Y[(size_t)row * Cc + lane + 32] = a1[r] + b[lane + 32];
    }
}

// ---------------- launch ----------------
extern "C" void kernel_launch(void* const* d_in, const int* in_sizes, int n_in,
                              void* d_out, int out_size)
{
    const float* feat  = (const float*)d_in[0];
    const int*   src   = (const int*)d_in[1];
    const int*   dst   = (const int*)d_in[2];
    const float* W_in  = (const float*)d_in[3];
    const float* b_in  = (const float*)d_in[4];
    const float* Wc    = (const float*)d_in[5];
    const float* bc    = (const float*)d_in[6];
    const float* gamma = (const float*)d_in[7];
    const float* beta  = (const float*)d_in[8];
    const float* rmean = (const float*)d_in[9];
    const float* rvar  = (const float*)d_in[10];
    const float* W_out = (const float*)d_in[11];
    const float* b_out = (const float*)d_in[12];
    float* out = (float*)d_out;

    float *ap = nullptr, *np = nullptr;
    __half* h16p = nullptr;
    cudaGetSymbolAddress((void**)&ap, g_agg);
    cudaGetSymbolAddress((void**)&np, g_nsrc);
    cudaGetSymbolAddress((void**)&h16p, g_h16);

    // lazy one-time side stream + fork/join events (no device memory involved)
    static cudaStream_t sB = nullptr;
    static cudaEvent_t evF = nullptr, evJ = nullptr;
    if (!sB) {
        cudaStreamCreateWithFlags(&sB, cudaStreamNonBlocking);
        cudaEventCreateWithFlags(&evF, cudaEventDisableTiming);
        cudaEventCreateWithFlags(&evJ, cudaEventDisableTiming);
    }

    const int NBLK = (Nn + 511) / 512;  // 196
    const size_t gemm_smem = (size_t)(128 * 128 + 64 * 128 + 256) * sizeof(float);
    cudaFuncSetAttribute(k_gemm128, cudaFuncAttributeMaxDynamicSharedMemorySize, (int)gemm_smem);

    // R11 topology: serial zero+deg, fork cheap CSR chain, norms+GEMM on stream 0.
    k_zero3<<<(Nn + 255) / 256, 256>>>();
    k_deg<<<(Ee + 255) / 256, 256>>>(src, dst);
    cudaEventRecord(evF, 0);

    cudaStreamWaitEvent(sB, evF, 0);
    k_scan1<<<NBLK, 512, 0, sB>>>();
    k_scan2<<<1, 32, 0, sB>>>(NBLK);
    k_scan3<<<NBLK, 512, 0, sB>>>();
    k_fill<<<(Ee + 255) / 256, 256, 0, sB>>>(src, dst);
    cudaEventRecord(evJ, sB);

    k_norms<<<(Nn + 255) / 256, 256>>>();
    k_gemm128<<<GPERS, 256, gemm_smem>>>(feat, W_in, b_in,
                                         gamma, beta, rmean, rvar, np, h16p);

    // join CSR build before first aggregation
    cudaStreamWaitEvent(0, evJ, 0);

    // 3 GraphConv layers
    for (int l = 0; l < Ll; l++) {
        k_agg<<<(Nn * 32 + 255) / 256, 256>>>();
        bool last = (l == Ll - 1);
        k_gemm128<<<GPERS, 256, gemm_smem>>>(ap, Wc + (size_t)l * Hh * Hh, bc + (size_t)l * Hh,
                                             gamma + (size_t)(l + 1) * Hh,
                                             beta  + (size_t)(l + 1) * Hh,
                                             rmean + (size_t)(l + 1) * Hh,
                                             rvar  + (size_t)(l + 1) * Hh,
                                             last ? nullptr : np, h16p);
    }

    // output projection (fp16 input)
    k_gemm_out<<<Nn / 32, 256>>>(h16p, W_out, b_out, out);
}